// round 5
// baseline (speedup 1.0000x reference)
#include <cuda_runtime.h>
#include <math.h>

// ---------------- Problem constants ----------------
#define Lq       1024
#define DMODEL   2048
#define DINNER   4096
#define DXB      1024
#define DSTATE   16
#define DTRANK   128
#define INTER    8192
#define NPROJ    (2*DINNER + 2*DXB + DTRANK)   // 10368

// ---------------- Scratch (static device globals; no allocation) ----------------
__device__ float g_xn  [Lq * DMODEL];   // rmsnorm1 output
__device__ float g_zx  [Lq * NPROJ];    // zxbcdt
__device__ float g_dt  [Lq * DINNER];   // softplus(dt)
__device__ float g_yg  [Lq * DINNER];   // scan output * silu(z)
__device__ float g_h   [Lq * DMODEL];   // residual after mamba
__device__ float g_hn  [Lq * DMODEL];   // rmsnorm2 output
__device__ float g_gate[Lq * INTER];    // silu(gate), later gate*up
__device__ float g_up  [Lq * INTER];

// ---------------- Helpers ----------------
__device__ __forceinline__ float siluf(float x) {
    return x / (1.f + __expf(-x));
}
__device__ __forceinline__ float softplusf(float x) {
    return (x > 20.f) ? x : log1pf(expf(x));
}

// ---------------- RMSNorm: one block per row, D=2048 ----------------
__global__ void rmsnorm_k(const float* __restrict__ x,
                          const float* __restrict__ w,
                          float* __restrict__ o)
{
    const int D = DMODEL;
    const int row = blockIdx.x;
    const float* xr = x + row * D;
    float ss = 0.f;
    for (int i = threadIdx.x * 4; i < D; i += 256 * 4) {
        float4 v = *(const float4*)(xr + i);
        ss += v.x*v.x + v.y*v.y + v.z*v.z + v.w*v.w;
    }
    #pragma unroll
    for (int off = 16; off > 0; off >>= 1)
        ss += __shfl_xor_sync(0xffffffffu, ss, off);
    __shared__ float sw[8];
    __shared__ float stot;
    if ((threadIdx.x & 31) == 0) sw[threadIdx.x >> 5] = ss;
    __syncthreads();
    if (threadIdx.x == 0) {
        float t = 0.f;
        #pragma unroll
        for (int i = 0; i < 8; i++) t += sw[i];
        stot = rsqrtf(t / (float)D + 1e-5f);
    }
    __syncthreads();
    const float rs = stot;
    for (int i = threadIdx.x * 4; i < D; i += 256 * 4) {
        float4 v  = *(const float4*)(xr + i);
        float4 wv = *(const float4*)(w + i);
        v.x *= rs * wv.x; v.y *= rs * wv.y; v.z *= rs * wv.z; v.w *= rs * wv.w;
        *(float4*)(o + row * D + i) = v;
    }
}

// ---------------- SGEMM: C[M,N] = A[M,K] * B[N,K]^T, fp32 ----------------
// BM=BN=128, BK=8, 256 threads, 8x8 per thread.
// EPI: 0=none, 1=softplus(acc + bias[n]), 2=acc + E[m,n], 3=silu(acc)
template<int EPI>
__global__ __launch_bounds__(256, 2)
void sgemm_k(int M, int N, int K,
             const float* __restrict__ A, int lda,
             const float* __restrict__ B, int ldb,
             float* __restrict__ C, int ldc,
             const float* __restrict__ E, int lde)
{
    const int BM = 128, BN = 128, BK = 8, TM = 8, TN = 8;
    __shared__ float As[BK][BM];
    __shared__ float Bs[BK][BN];

    const int tid = threadIdx.x;
    const int m0 = blockIdx.y * BM;
    const int n0 = blockIdx.x * BN;

    const int arow = tid >> 1;           // 0..127
    const int acol = (tid & 1) << 2;     // 0 or 4
    const float* Aptr = A + (size_t)(m0 + arow) * lda + acol;
    const float* Bptr = B + (size_t)(n0 + arow) * ldb + acol;

    const int trow = (tid >> 4) * TM;    // 0..120
    const int tcol = (tid & 15) * TN;    // 0..120

    float acc[TM][TN];
    #pragma unroll
    for (int i = 0; i < TM; i++)
        #pragma unroll
        for (int j = 0; j < TN; j++) acc[i][j] = 0.f;

    for (int k0 = 0; k0 < K; k0 += BK) {
        float4 a4 = *(const float4*)(Aptr + k0);
        float4 b4 = *(const float4*)(Bptr + k0);
        As[acol + 0][arow] = a4.x;
        As[acol + 1][arow] = a4.y;
        As[acol + 2][arow] = a4.z;
        As[acol + 3][arow] = a4.w;
        Bs[acol + 0][arow] = b4.x;
        Bs[acol + 1][arow] = b4.y;
        Bs[acol + 2][arow] = b4.z;
        Bs[acol + 3][arow] = b4.w;
        __syncthreads();

        #pragma unroll
        for (int kk = 0; kk < BK; kk++) {
            float ra[TM], rb[TN];
            *(float4*)&ra[0] = *(const float4*)&As[kk][trow];
            *(float4*)&ra[4] = *(const float4*)&As[kk][trow + 4];
            *(float4*)&rb[0] = *(const float4*)&Bs[kk][tcol];
            *(float4*)&rb[4] = *(const float4*)&Bs[kk][tcol + 4];
            #pragma unroll
            for (int i = 0; i < TM; i++)
                #pragma unroll
                for (int j = 0; j < TN; j++)
                    acc[i][j] = fmaf(ra[i], rb[j], acc[i][j]);
        }
        __syncthreads();
    }

    // Epilogue
    #pragma unroll
    for (int i = 0; i < TM; i++) {
        const int gm = m0 + trow + i;
        #pragma unroll
        for (int jb = 0; jb < TN; jb += 4) {
            const int gn = n0 + tcol + jb;
            float4 v = make_float4(acc[i][jb], acc[i][jb+1], acc[i][jb+2], acc[i][jb+3]);
            if (EPI == 1) {
                v.x = softplusf(v.x + E[gn + 0]);
                v.y = softplusf(v.y + E[gn + 1]);
                v.z = softplusf(v.z + E[gn + 2]);
                v.w = softplusf(v.w + E[gn + 3]);
            } else if (EPI == 2) {
                float4 e = *(const float4*)(E + (size_t)gm * lde + gn);
                v.x += e.x; v.y += e.y; v.z += e.z; v.w += e.w;
            } else if (EPI == 3) {
                v.x = siluf(v.x); v.y = siluf(v.y); v.z = siluf(v.z); v.w = siluf(v.w);
            }
            *(float4*)(C + (size_t)gm * ldc + gn) = v;
        }
    }
}

// ---------------- Selective scan ----------------
// 4 threads per channel (16384 threads). Each thread owns 4 states in registers.
// zx row layout: [0,4096) z | [4096,5120) xv | [5120,6144) B | [6144,10240) C | [10240,10368) dt_in
__global__ void scan_k(const float* __restrict__ zx,
                       const float* __restrict__ dt,
                       const float* __restrict__ A_log,
                       const float* __restrict__ D_skip,
                       float* __restrict__ yg)
{
    const int tid = blockIdx.x * blockDim.x + threadIdx.x;  // 0..16383
    const int ch = tid >> 2;          // channel d in [0,4096)
    const int s  = tid & 3;           // state group (4 states each)

    const int src  = ((ch >> 6) << 4) + (ch & 15);            // xv index
    const int boff = 5120 + ((ch >> 6) << 4) + (s << 2);      // B values for states s*4..s*4+3
    const int coff = 6144 + (ch & ~15) + (s << 2);            // C values

    const float a0 = -expf(A_log[ch * DSTATE + s * 4 + 0]);
    const float a1 = -expf(A_log[ch * DSTATE + s * 4 + 1]);
    const float a2 = -expf(A_log[ch * DSTATE + s * 4 + 2]);
    const float a3 = -expf(A_log[ch * DSTATE + s * 4 + 3]);
    const float dsk = D_skip[ch];

    float h0 = 0.f, h1 = 0.f, h2 = 0.f, h3 = 0.f;
    const float* row = zx;

    for (int l = 0; l < Lq; l++, row += NPROJ) {
        const float dtv = dt[l * DINNER + ch];
        const float xv  = row[4096 + src];
        const float4 B  = *(const float4*)(row + boff);
        const float4 Cv = *(const float4*)(row + coff);
        const float dtx = dtv * xv;

        h0 = __expf(dtv * a0) * h0 + dtx * B.x;
        h1 = __expf(dtv * a1) * h1 + dtx * B.y;
        h2 = __expf(dtv * a2) * h2 + dtx * B.z;
        h3 = __expf(dtv * a3) * h3 + dtx * B.w;

        float yp = Cv.x * h0 + Cv.y * h1 + Cv.z * h2 + Cv.w * h3;
        yp += __shfl_xor_sync(0xffffffffu, yp, 1);
        yp += __shfl_xor_sync(0xffffffffu, yp, 2);

        if (s == 0) {
            const float z = row[ch];
            float v = yp + dsk * xv;
            v *= z / (1.f + __expf(-z));
            yg[l * DINNER + ch] = v;
        }
    }
}

// ---------------- Elementwise multiply (gate *= up) ----------------
__global__ void mul_k(float* __restrict__ g, const float* __restrict__ u, int n4)
{
    const int i = blockIdx.x * blockDim.x + threadIdx.x;
    if (i < n4) {
        float4 a = ((const float4*)g)[i];
        float4 b = ((const float4*)u)[i];
        a.x *= b.x; a.y *= b.y; a.z *= b.z; a.w *= b.w;
        ((float4*)g)[i] = a;
    }
}

// ---------------- Launch ----------------
extern "C" void kernel_launch(void* const* d_in, const int* in_sizes, int n_in,
                              void* d_out, int out_size)
{
    const float* hidden     = (const float*)d_in[0];
    const float* rms1_w     = (const float*)d_in[1];
    const float* in_proj_w  = (const float*)d_in[2];
    const float* dt_proj_w  = (const float*)d_in[3];
    const float* dt_proj_b  = (const float*)d_in[4];
    const float* A_log      = (const float*)d_in[5];
    const float* D_skip     = (const float*)d_in[6];
    const float* out_proj_w = (const float*)d_in[7];
    const float* rms2_w     = (const float*)d_in[8];
    const float* gate_w     = (const float*)d_in[9];
    const float* up_w       = (const float*)d_in[10];
    const float* down_w     = (const float*)d_in[11];
    float* out = (float*)d_out;

    float *xn, *zx, *dt, *yg, *h, *hn, *gb, *ub;
    cudaGetSymbolAddress((void**)&xn, g_xn);
    cudaGetSymbolAddress((void**)&zx, g_zx);
    cudaGetSymbolAddress((void**)&dt, g_dt);
    cudaGetSymbolAddress((void**)&yg, g_yg);
    cudaGetSymbolAddress((void**)&h,  g_h);
    cudaGetSymbolAddress((void**)&hn, g_hn);
    cudaGetSymbolAddress((void**)&gb, g_gate);
    cudaGetSymbolAddress((void**)&ub, g_up);

    // 1. rmsnorm1
    rmsnorm_k<<<Lq, 256>>>(hidden, rms1_w, xn);

    // 2. in_proj: (1024x2048) @ (10368x2048)^T -> zxbcdt
    sgemm_k<0><<<dim3(NPROJ/128, Lq/128), 256>>>(Lq, NPROJ, DMODEL,
        xn, DMODEL, in_proj_w, DMODEL, zx, NPROJ, nullptr, 0);

    // 3. dt = softplus(dt_in @ dt_proj_w^T + b)
    sgemm_k<1><<<dim3(DINNER/128, Lq/128), 256>>>(Lq, DINNER, DTRANK,
        zx + 2*DINNER + 2*DXB, NPROJ, dt_proj_w, DTRANK, dt, DINNER, dt_proj_b, 0);

    // 4. selective scan (includes +D_skip*x and *silu(z))
    scan_k<<<64, 256>>>(zx, dt, A_log, D_skip, yg);

    // 5. out_proj + residual
    sgemm_k<2><<<dim3(DMODEL/128, Lq/128), 256>>>(Lq, DMODEL, DINNER,
        yg, DINNER, out_proj_w, DINNER, h, DMODEL, hidden, DMODEL);

    // 6. rmsnorm2
    rmsnorm_k<<<Lq, 256>>>(h, rms2_w, hn);

    // 7. gate = silu(hn @ gate_w^T)
    sgemm_k<3><<<dim3(INTER/128, Lq/128), 256>>>(Lq, INTER, DMODEL,
        hn, DMODEL, gate_w, DMODEL, gb, INTER, nullptr, 0);

    // 8. up = hn @ up_w^T
    sgemm_k<0><<<dim3(INTER/128, Lq/128), 256>>>(Lq, INTER, DMODEL,
        hn, DMODEL, up_w, DMODEL, ub, INTER, nullptr, 0);

    // 9. gate *= up
    mul_k<<<(Lq*INTER/4 + 255)/256, 256>>>(gb, ub, Lq*INTER/4);

    // 10. down proj + residual -> output
    sgemm_k<2><<<dim3(DMODEL/128, Lq/128), 256>>>(Lq, DMODEL, INTER,
        gb, INTER, down_w, INTER, out, DMODEL, h, DMODEL);
}

// round 11
// speedup vs baseline: 2.5074x; 2.5074x over previous
#include <cuda_runtime.h>
#include <cuda_bf16.h>
#include <math.h>
#include <stdint.h>

// ---------------- Problem constants ----------------
#define Lq       1024
#define DMODEL   2048
#define DINNER   4096
#define DXB      1024
#define DSTATE   16
#define DTRANK   128
#define INTER    8192
#define NPROJ    (2*DINNER + 2*DXB + DTRANK)   // 10368

// ---------------- fp32 scratch ----------------
__device__ __align__(16) float g_xn[Lq*DMODEL];
__device__ __align__(16) float g_zx[Lq*NPROJ];
__device__ __align__(16) float g_dt[Lq*DINNER];
__device__ __align__(16) float g_yg[Lq*DINNER];
__device__ __align__(16) float g_h [Lq*DMODEL];
__device__ __align__(16) float g_hn[Lq*DMODEL];
__device__ __align__(16) float g_gb[Lq*INTER];
__device__ __align__(16) float g_ub[Lq*INTER];

// ---------------- bf16 split planes (hi / lo) ----------------
__device__ __align__(16) __nv_bfloat16 g_xnH[Lq*DMODEL],  g_xnL[Lq*DMODEL];
__device__ __align__(16) __nv_bfloat16 g_dtiH[Lq*DTRANK], g_dtiL[Lq*DTRANK];
__device__ __align__(16) __nv_bfloat16 g_ygH[Lq*DINNER],  g_ygL[Lq*DINNER];
__device__ __align__(16) __nv_bfloat16 g_hnH[Lq*DMODEL],  g_hnL[Lq*DMODEL];
__device__ __align__(16) __nv_bfloat16 g_gpH[Lq*INTER],   g_gpL[Lq*INTER];
__device__ __align__(16) __nv_bfloat16 g_wInH[NPROJ*DMODEL],  g_wInL[NPROJ*DMODEL];
__device__ __align__(16) __nv_bfloat16 g_wDtH[DINNER*DTRANK], g_wDtL[DINNER*DTRANK];
__device__ __align__(16) __nv_bfloat16 g_wOutH[DMODEL*DINNER],g_wOutL[DMODEL*DINNER];
__device__ __align__(16) __nv_bfloat16 g_wGH[INTER*DMODEL],   g_wGL[INTER*DMODEL];
__device__ __align__(16) __nv_bfloat16 g_wUH[INTER*DMODEL],   g_wUL[INTER*DMODEL];
__device__ __align__(16) __nv_bfloat16 g_wDH[DMODEL*INTER],   g_wDL[DMODEL*INTER];

// ---------------- helpers ----------------
__device__ __forceinline__ uint32_t smem_u32(const void* p) {
    uint32_t a;
    asm("{ .reg .u64 t; cvta.to.shared.u64 t, %1; cvt.u32.u64 %0, t; }" : "=r"(a) : "l"(p));
    return a;
}
#define SWZ(o) ((o) ^ (((o) >> 3) & 0x70))

__device__ __forceinline__ float siluf(float x)     { return x / (1.f + __expf(-x)); }
__device__ __forceinline__ float softplusf(float x) { return (x > 20.f) ? x : log1pf(expf(x)); }

#define LDSM4(r, addr) \
    asm volatile("ldmatrix.sync.aligned.m8n8.x4.shared.b16 {%0,%1,%2,%3}, [%4];" \
        : "=r"((r)[0]), "=r"((r)[1]), "=r"((r)[2]), "=r"((r)[3]) : "r"(addr))

#define MMA16816(c, a, b) \
    asm volatile("mma.sync.aligned.m16n8k16.row.col.f32.bf16.bf16.f32 " \
        "{%0,%1,%2,%3}, {%4,%5,%6,%7}, {%8,%9}, {%0,%1,%2,%3};" \
        : "+f"((c)[0]), "+f"((c)[1]), "+f"((c)[2]), "+f"((c)[3]) \
        : "r"((a)[0]), "r"((a)[1]), "r"((a)[2]), "r"((a)[3]), "r"((b)[0]), "r"((b)[1]))

// ---------------- RMSNorm ----------------
__global__ void rmsnorm_k(const float* __restrict__ x, const float* __restrict__ w,
                          float* __restrict__ o)
{
    const int D = DMODEL;
    const int row = blockIdx.x;
    const float* xr = x + row * D;
    float ss = 0.f;
    for (int i = threadIdx.x * 4; i < D; i += 256 * 4) {
        float4 v = *(const float4*)(xr + i);
        ss += v.x*v.x + v.y*v.y + v.z*v.z + v.w*v.w;
    }
    #pragma unroll
    for (int off = 16; off > 0; off >>= 1) ss += __shfl_xor_sync(0xffffffffu, ss, off);
    __shared__ float sw[8]; __shared__ float stot;
    if ((threadIdx.x & 31) == 0) sw[threadIdx.x >> 5] = ss;
    __syncthreads();
    if (threadIdx.x == 0) {
        float t = 0.f;
        #pragma unroll
        for (int i = 0; i < 8; i++) t += sw[i];
        stot = rsqrtf(t / (float)D + 1e-5f);
    }
    __syncthreads();
    const float rs = stot;
    for (int i = threadIdx.x * 4; i < D; i += 256 * 4) {
        float4 v = *(const float4*)(xr + i);
        float4 wv = *(const float4*)(w + i);
        v.x *= rs*wv.x; v.y *= rs*wv.y; v.z *= rs*wv.z; v.w *= rs*wv.w;
        *(float4*)(o + row * D + i) = v;
    }
}

// ---------------- bf16 split kernels ----------------
__device__ __forceinline__ void split4(float4 v, __nv_bfloat16* h, __nv_bfloat16* l, int i) {
    __nv_bfloat16 h0 = __float2bfloat16(v.x), h1 = __float2bfloat16(v.y);
    __nv_bfloat16 h2 = __float2bfloat16(v.z), h3 = __float2bfloat16(v.w);
    __nv_bfloat162 a, b; a.x = h0; a.y = h1; b.x = h2; b.y = h3;
    ((__nv_bfloat162*)h)[2*i]   = a;
    ((__nv_bfloat162*)h)[2*i+1] = b;
    __nv_bfloat162 c, d;
    c.x = __float2bfloat16(v.x - __bfloat162float(h0));
    c.y = __float2bfloat16(v.y - __bfloat162float(h1));
    d.x = __float2bfloat16(v.z - __bfloat162float(h2));
    d.y = __float2bfloat16(v.w - __bfloat162float(h3));
    ((__nv_bfloat162*)l)[2*i]   = c;
    ((__nv_bfloat162*)l)[2*i+1] = d;
}

__global__ void split_k(const float* __restrict__ x,
                        __nv_bfloat16* __restrict__ h, __nv_bfloat16* __restrict__ l, int n4)
{
    int i = blockIdx.x * blockDim.x + threadIdx.x;
    if (i < n4) split4(((const float4*)x)[i], h, l, i);
}

__global__ void split2d_k(const float* __restrict__ x, int ld, int cols4,
                          __nv_bfloat16* __restrict__ h, __nv_bfloat16* __restrict__ l, int n4)
{
    int i = blockIdx.x * blockDim.x + threadIdx.x;
    if (i < n4) {
        int row = i / cols4, c = i % cols4;
        float4 v = *(const float4*)(x + (size_t)row * ld + c * 4);
        split4(v, h, l, i);
    }
}

__global__ void splitmul_k(const float* __restrict__ g, const float* __restrict__ u,
                           __nv_bfloat16* __restrict__ h, __nv_bfloat16* __restrict__ l, int n4)
{
    int i = blockIdx.x * blockDim.x + threadIdx.x;
    if (i < n4) {
        float4 a = ((const float4*)g)[i];
        float4 b = ((const float4*)u)[i];
        a.x *= b.x; a.y *= b.y; a.z *= b.z; a.w *= b.w;
        split4(a, h, l, i);
    }
}

// ---------------- cp.async plane loader: 128 rows x 128B, SW128 swizzled ----------------
__device__ __forceinline__ void ldp(uint32_t sdst, const __nv_bfloat16* __restrict__ g,
                                    int ld, int row0, int k0, int tid)
{
    #pragma unroll
    for (int i = tid; i < 1024; i += 256) {
        int r = i >> 3, u = i & 7;
        const void* src = g + (size_t)(row0 + r) * ld + k0 + u * 8;
        uint32_t dst = sdst + SWZ(r * 128 + u * 16);
        asm volatile("cp.async.cg.shared.global [%0], [%1], 16;" :: "r"(dst), "l"(src));
    }
}

// ---------------- bf16x3 split-precision GEMM via mma.sync ----------------
// C[M,N] = (Ah+Al)[M,K] * (Bh+Bl)[N,K]^T, fp32 accum.
// BM=BN=128, BK=64. 8 warps (2x4), warp tile 64x32 (4x4 m16n8k16).
// EPI: 0=none, 1=softplus(acc+bias[n]), 2=acc+E[m,n], 3=silu(acc)
template<int EPI>
__global__ __launch_bounds__(256, 1)
void gemm_mma(int K,
              const __nv_bfloat16* __restrict__ AH, const __nv_bfloat16* __restrict__ AL,
              const __nv_bfloat16* __restrict__ BH, const __nv_bfloat16* __restrict__ BL,
              float* __restrict__ C, int ldc,
              const float* __restrict__ E, int lde)
{
    extern __shared__ char sm[];
    const int tid = threadIdx.x, wid = tid >> 5, lane = tid & 31;
    const int m0 = blockIdx.x * 128, n0 = blockIdx.y * 128;
    const int wr = wid >> 2, wc = wid & 3;   // warp grid 2x4
    const uint32_t sb = smem_u32(sm);
    constexpr uint32_t PB = 16384, BUF = 4 * PB;

    float acc[4][4][4];
    #pragma unroll
    for (int a = 0; a < 4; a++)
        #pragma unroll
        for (int b = 0; b < 4; b++)
            #pragma unroll
            for (int c = 0; c < 4; c++) acc[a][b][c] = 0.f;

    const int NC = K >> 6;

    // prologue: chunk 0 -> buffer 0
    ldp(sb + 0*PB, AH, K, m0, 0, tid);
    ldp(sb + 1*PB, AL, K, m0, 0, tid);
    ldp(sb + 2*PB, BH, K, n0, 0, tid);
    ldp(sb + 3*PB, BL, K, n0, 0, tid);
    asm volatile("cp.async.commit_group;");

    for (int c = 0; c < NC; c++) {
        const uint32_t base = sb + (uint32_t)(c & 1) * BUF;
        if (c + 1 < NC) {
            const uint32_t nb = sb + (uint32_t)((c + 1) & 1) * BUF;
            const int k0 = (c + 1) << 6;
            ldp(nb + 0*PB, AH, K, m0, k0, tid);
            ldp(nb + 1*PB, AL, K, m0, k0, tid);
            ldp(nb + 2*PB, BH, K, n0, k0, tid);
            ldp(nb + 3*PB, BL, K, n0, k0, tid);
            asm volatile("cp.async.commit_group;");
            asm volatile("cp.async.wait_group 1;");
        } else {
            asm volatile("cp.async.wait_group 0;");
        }
        __syncthreads();

        #pragma unroll
        for (int ks = 0; ks < 4; ks++) {
            uint32_t ah[4][4], al[4][4], bh[4][2], bl[4][2];
            // A fragments
            {
                const int row = wr * 64 + (lane & 15);
                const int ku  = ks * 2 + (lane >> 4);
                #pragma unroll
                for (int mt = 0; mt < 4; mt++) {
                    const uint32_t off = SWZ((row + mt * 16) * 128 + ku * 16);
                    LDSM4(ah[mt], base + 0*PB + off);
                    LDSM4(al[mt], base + 1*PB + off);
                }
            }
            // B fragments: each x4 covers two n8 tiles
            {
                const int rn = wc * 32 + (lane & 7) + ((lane >> 4) & 1) * 8;
                const int ku = ks * 2 + ((lane >> 3) & 1);
                #pragma unroll
                for (int p = 0; p < 2; p++) {
                    const uint32_t off = SWZ((rn + p * 16) * 128 + ku * 16);
                    uint32_t t[4];
                    LDSM4(t, base + 2*PB + off);
                    bh[p*2][0] = t[0]; bh[p*2][1] = t[1];
                    bh[p*2+1][0] = t[2]; bh[p*2+1][1] = t[3];
                    LDSM4(t, base + 3*PB + off);
                    bl[p*2][0] = t[0]; bl[p*2][1] = t[1];
                    bl[p*2+1][0] = t[2]; bl[p*2+1][1] = t[3];
                }
            }
            #pragma unroll
            for (int mt = 0; mt < 4; mt++)
                #pragma unroll
                for (int nt = 0; nt < 4; nt++) {
                    MMA16816(acc[mt][nt], ah[mt], bh[nt]);
                    MMA16816(acc[mt][nt], ah[mt], bl[nt]);
                    MMA16816(acc[mt][nt], al[mt], bh[nt]);
                }
        }
        __syncthreads();
    }

    // Epilogue: lane l holds (row = l/4 [+8], cols = (l%4)*2, +1)
    #pragma unroll
    for (int mt = 0; mt < 4; mt++) {
        #pragma unroll
        for (int nt = 0; nt < 4; nt++) {
            const int gm = m0 + wr * 64 + mt * 16 + (lane >> 2);
            const int gn = n0 + wc * 32 + nt * 8 + (lane & 3) * 2;
            #pragma unroll
            for (int half = 0; half < 2; half++) {
                const int row = gm + half * 8;
                float2 v = make_float2(acc[mt][nt][half*2], acc[mt][nt][half*2+1]);
                if (EPI == 1) {
                    const float2 b = *(const float2*)(E + gn);
                    v.x = softplusf(v.x + b.x); v.y = softplusf(v.y + b.y);
                } else if (EPI == 2) {
                    const float2 e = *(const float2*)(E + (size_t)row * lde + gn);
                    v.x += e.x; v.y += e.y;
                } else if (EPI == 3) {
                    v.x = siluf(v.x); v.y = siluf(v.y);
                }
                *(float2*)(C + (size_t)row * ldc + gn) = v;
            }
        }
    }
}

// ---------------- Selective scan (verified) ----------------
__global__ void scan_k(const float* __restrict__ zx, const float* __restrict__ dt,
                       const float* __restrict__ A_log, const float* __restrict__ D_skip,
                       float* __restrict__ yg)
{
    const int tid = blockIdx.x * blockDim.x + threadIdx.x;
    const int ch = tid >> 2;
    const int s  = tid & 3;

    const int src  = ((ch >> 6) << 4) + (ch & 15);
    const int boff = 5120 + ((ch >> 6) << 4) + (s << 2);
    const int coff = 6144 + (ch & ~15) + (s << 2);

    const float a0 = -expf(A_log[ch * DSTATE + s * 4 + 0]);
    const float a1 = -expf(A_log[ch * DSTATE + s * 4 + 1]);
    const float a2 = -expf(A_log[ch * DSTATE + s * 4 + 2]);
    const float a3 = -expf(A_log[ch * DSTATE + s * 4 + 3]);
    const float dsk = D_skip[ch];

    float h0 = 0.f, h1 = 0.f, h2 = 0.f, h3 = 0.f;
    const float* row = zx;
    for (int l = 0; l < Lq; l++, row += NPROJ) {
        const float dtv = dt[l * DINNER + ch];
        const float xv  = row[4096 + src];
        const float4 B  = *(const float4*)(row + boff);
        const float4 Cv = *(const float4*)(row + coff);
        const float dtx = dtv * xv;

        h0 = __expf(dtv * a0) * h0 + dtx * B.x;
        h1 = __expf(dtv * a1) * h1 + dtx * B.y;
        h2 = __expf(dtv * a2) * h2 + dtx * B.z;
        h3 = __expf(dtv * a3) * h3 + dtx * B.w;

        float yp = Cv.x * h0 + Cv.y * h1 + Cv.z * h2 + Cv.w * h3;
        yp += __shfl_xor_sync(0xffffffffu, yp, 1);
        yp += __shfl_xor_sync(0xffffffffu, yp, 2);

        if (s == 0) {
            const float z = row[ch];
            float v = yp + dsk * xv;
            v *= z / (1.f + __expf(-z));
            yg[l * DINNER + ch] = v;
        }
    }
}

// ---------------- Launch ----------------
extern "C" void kernel_launch(void* const* d_in, const int* in_sizes, int n_in,
                              void* d_out, int out_size)
{
    const float* hidden     = (const float*)d_in[0];
    const float* rms1_w     = (const float*)d_in[1];
    const float* in_proj_w  = (const float*)d_in[2];
    const float* dt_proj_w  = (const float*)d_in[3];
    const float* dt_proj_b  = (const float*)d_in[4];
    const float* A_log      = (const float*)d_in[5];
    const float* D_skip     = (const float*)d_in[6];
    const float* out_proj_w = (const float*)d_in[7];
    const float* rms2_w     = (const float*)d_in[8];
    const float* gate_w     = (const float*)d_in[9];
    const float* up_w       = (const float*)d_in[10];
    const float* down_w     = (const float*)d_in[11];
    float* out = (float*)d_out;

    float *xn, *zx, *dt, *yg, *h, *hn, *gb, *ub;
    cudaGetSymbolAddress((void**)&xn, g_xn);
    cudaGetSymbolAddress((void**)&zx, g_zx);
    cudaGetSymbolAddress((void**)&dt, g_dt);
    cudaGetSymbolAddress((void**)&yg, g_yg);
    cudaGetSymbolAddress((void**)&h,  g_h);
    cudaGetSymbolAddress((void**)&hn, g_hn);
    cudaGetSymbolAddress((void**)&gb, g_gb);
    cudaGetSymbolAddress((void**)&ub, g_ub);

    __nv_bfloat16 *xnH,*xnL,*dtiH,*dtiL,*ygH,*ygL,*hnH,*hnL,*gpH,*gpL;
    __nv_bfloat16 *wInH,*wInL,*wDtH,*wDtL,*wOutH,*wOutL,*wGH,*wGL,*wUH,*wUL,*wDH,*wDL;
    cudaGetSymbolAddress((void**)&xnH,  g_xnH);  cudaGetSymbolAddress((void**)&xnL,  g_xnL);
    cudaGetSymbolAddress((void**)&dtiH, g_dtiH); cudaGetSymbolAddress((void**)&dtiL, g_dtiL);
    cudaGetSymbolAddress((void**)&ygH,  g_ygH);  cudaGetSymbolAddress((void**)&ygL,  g_ygL);
    cudaGetSymbolAddress((void**)&hnH,  g_hnH);  cudaGetSymbolAddress((void**)&hnL,  g_hnL);
    cudaGetSymbolAddress((void**)&gpH,  g_gpH);  cudaGetSymbolAddress((void**)&gpL,  g_gpL);
    cudaGetSymbolAddress((void**)&wInH, g_wInH); cudaGetSymbolAddress((void**)&wInL, g_wInL);
    cudaGetSymbolAddress((void**)&wDtH, g_wDtH); cudaGetSymbolAddress((void**)&wDtL, g_wDtL);
    cudaGetSymbolAddress((void**)&wOutH,g_wOutH);cudaGetSymbolAddress((void**)&wOutL,g_wOutL);
    cudaGetSymbolAddress((void**)&wGH,  g_wGH);  cudaGetSymbolAddress((void**)&wGL,  g_wGL);
    cudaGetSymbolAddress((void**)&wUH,  g_wUH);  cudaGetSymbolAddress((void**)&wUL,  g_wUL);
    cudaGetSymbolAddress((void**)&wDH,  g_wDH);  cudaGetSymbolAddress((void**)&wDL,  g_wDL);

    const int SMEM = 2 * 4 * 16384;  // 131072
    cudaFuncSetAttribute(gemm_mma<0>, cudaFuncAttributeMaxDynamicSharedMemorySize, SMEM);
    cudaFuncSetAttribute(gemm_mma<1>, cudaFuncAttributeMaxDynamicSharedMemorySize, SMEM);
    cudaFuncSetAttribute(gemm_mma<2>, cudaFuncAttributeMaxDynamicSharedMemorySize, SMEM);
    cudaFuncSetAttribute(gemm_mma<3>, cudaFuncAttributeMaxDynamicSharedMemorySize, SMEM);

    // --- weight splits (memory-bound, ~110us total) ---
    split_k<<<(NPROJ*DMODEL/4 + 255)/256, 256>>>(in_proj_w, wInH, wInL, NPROJ*DMODEL/4);
    split_k<<<(DINNER*DTRANK/4 + 255)/256, 256>>>(dt_proj_w, wDtH, wDtL, DINNER*DTRANK/4);
    split_k<<<(DMODEL*DINNER/4 + 255)/256, 256>>>(out_proj_w, wOutH, wOutL, DMODEL*DINNER/4);
    split_k<<<(INTER*DMODEL/4 + 255)/256, 256>>>(gate_w, wGH, wGL, INTER*DMODEL/4);
    split_k<<<(INTER*DMODEL/4 + 255)/256, 256>>>(up_w, wUH, wUL, INTER*DMODEL/4);
    split_k<<<(DMODEL*INTER/4 + 255)/256, 256>>>(down_w, wDH, wDL, DMODEL*INTER/4);

    // 1. rmsnorm1 + split
    rmsnorm_k<<<Lq, 256>>>(hidden, rms1_w, xn);
    split_k<<<(Lq*DMODEL/4 + 255)/256, 256>>>(xn, xnH, xnL, Lq*DMODEL/4);

    // 2. in_proj: [1024 x 10368], K=2048
    gemm_mma<0><<<dim3(Lq/128, NPROJ/128), 256, SMEM>>>(
        DMODEL, xnH, xnL, wInH, wInL, zx, NPROJ, nullptr, 0);

    // 3. dt = softplus(dt_in @ dt_proj^T + b), K=128
    split2d_k<<<(Lq*DTRANK/4 + 255)/256, 256>>>(
        zx + 2*DINNER + 2*DXB, NPROJ, DTRANK/4, dtiH, dtiL, Lq*DTRANK/4);
    gemm_mma<1><<<dim3(Lq/128, DINNER/128), 256, SMEM>>>(
        DTRANK, dtiH, dtiL, wDtH, wDtL, dt, DINNER, dt_proj_b, 0);

    // 4. selective scan
    scan_k<<<64, 256>>>(zx, dt, A_log, D_skip, yg);

    // 5. out_proj + residual, K=4096
    split_k<<<(Lq*DINNER/4 + 255)/256, 256>>>(yg, ygH, ygL, Lq*DINNER/4);
    gemm_mma<2><<<dim3(Lq/128, DMODEL/128), 256, SMEM>>>(
        DINNER, ygH, ygL, wOutH, wOutL, h, DMODEL, hidden, DMODEL);

    // 6. rmsnorm2 + split
    rmsnorm_k<<<Lq, 256>>>(h, rms2_w, hn);
    split_k<<<(Lq*DMODEL/4 + 255)/256, 256>>>(hn, hnH, hnL, Lq*DMODEL/4);

    // 7/8. gate = silu(hn @ gate^T), up = hn @ up^T, K=2048
    gemm_mma<3><<<dim3(Lq/128, INTER/128), 256, SMEM>>>(
        DMODEL, hnH, hnL, wGH, wGL, gb, INTER, nullptr, 0);
    gemm_mma<0><<<dim3(Lq/128, INTER/128), 256, SMEM>>>(
        DMODEL, hnH, hnL, wUH, wUL, ub, INTER, nullptr, 0);

    // 9. (gate*up) -> bf16 split
    splitmul_k<<<(Lq*INTER/4 + 255)/256, 256>>>(gb, ub, gpH, gpL, Lq*INTER/4);

    // 10. down proj + residual -> out, K=8192
    gemm_mma<2><<<dim3(Lq/128, DMODEL/128), 256, SMEM>>>(
        INTER, gpH, gpL, wDH, wDL, out, DMODEL, h, DMODEL);
}

// round 13
// speedup vs baseline: 2.5103x; 1.0011x over previous
#include <cuda_runtime.h>
#include <cuda_bf16.h>
#include <math.h>
#include <stdint.h>

// ---------------- Problem constants ----------------
#define Lq       1024
#define DMODEL   2048
#define DINNER   4096
#define DXB      1024
#define DSTATE   16
#define DTRANK   128
#define INTER    8192
#define NPROJ    (2*DINNER + 2*DXB + DTRANK)   // 10368

// ---------------- fp32 scratch ----------------
__device__ __align__(16) float g_xn[Lq*DMODEL];
__device__ __align__(16) float g_zx[Lq*NPROJ];
__device__ __align__(16) float g_dt[Lq*DINNER];
__device__ __align__(16) float g_yg[Lq*DINNER];
__device__ __align__(16) float g_h [Lq*DMODEL];
__device__ __align__(16) float g_hn[Lq*DMODEL];
__device__ __align__(16) float g_gb[Lq*INTER];
__device__ __align__(16) float g_ub[Lq*INTER];

// ---------------- bf16 split planes (hi / lo) ----------------
__device__ __align__(16) __nv_bfloat16 g_xnH[Lq*DMODEL],  g_xnL[Lq*DMODEL];
__device__ __align__(16) __nv_bfloat16 g_dtiH[Lq*DTRANK], g_dtiL[Lq*DTRANK];
__device__ __align__(16) __nv_bfloat16 g_ygH[Lq*DINNER],  g_ygL[Lq*DINNER];
__device__ __align__(16) __nv_bfloat16 g_hnH[Lq*DMODEL],  g_hnL[Lq*DMODEL];
__device__ __align__(16) __nv_bfloat16 g_gpH[Lq*INTER],   g_gpL[Lq*INTER];
__device__ __align__(16) __nv_bfloat16 g_wInH[NPROJ*DMODEL],  g_wInL[NPROJ*DMODEL];
__device__ __align__(16) __nv_bfloat16 g_wDtH[DINNER*DTRANK], g_wDtL[DINNER*DTRANK];
__device__ __align__(16) __nv_bfloat16 g_wOutH[DMODEL*DINNER],g_wOutL[DMODEL*DINNER];
__device__ __align__(16) __nv_bfloat16 g_wGH[INTER*DMODEL],   g_wGL[INTER*DMODEL];
__device__ __align__(16) __nv_bfloat16 g_wUH[INTER*DMODEL],   g_wUL[INTER*DMODEL];
__device__ __align__(16) __nv_bfloat16 g_wDH[DMODEL*INTER],   g_wDL[DMODEL*INTER];

// ---------------- helpers ----------------
__device__ __forceinline__ uint32_t smem_u32(const void* p) {
    uint32_t a;
    asm("{ .reg .u64 t; cvta.to.shared.u64 t, %1; cvt.u32.u64 %0, t; }" : "=r"(a) : "l"(p));
    return a;
}
#define SWZ(o) ((o) ^ (((o) >> 3) & 0x70))

__device__ __forceinline__ float siluf(float x)     { return x / (1.f + __expf(-x)); }
__device__ __forceinline__ float softplusf(float x) { return (x > 20.f) ? x : log1pf(expf(x)); }

#define LDSM4(r, addr) \
    asm volatile("ldmatrix.sync.aligned.m8n8.x4.shared.b16 {%0,%1,%2,%3}, [%4];" \
        : "=r"((r)[0]), "=r"((r)[1]), "=r"((r)[2]), "=r"((r)[3]) : "r"(addr))

#define MMA16816(c, a, b) \
    asm volatile("mma.sync.aligned.m16n8k16.row.col.f32.bf16.bf16.f32 " \
        "{%0,%1,%2,%3}, {%4,%5,%6,%7}, {%8,%9}, {%0,%1,%2,%3};" \
        : "+f"((c)[0]), "+f"((c)[1]), "+f"((c)[2]), "+f"((c)[3]) \
        : "r"((a)[0]), "r"((a)[1]), "r"((a)[2]), "r"((a)[3]), "r"((b)[0]), "r"((b)[1]))

// ---------------- RMSNorm ----------------
__global__ void rmsnorm_k(const float* __restrict__ x, const float* __restrict__ w,
                          float* __restrict__ o)
{
    const int D = DMODEL;
    const int row = blockIdx.x;
    const float* xr = x + row * D;
    float ss = 0.f;
    for (int i = threadIdx.x * 4; i < D; i += 256 * 4) {
        float4 v = *(const float4*)(xr + i);
        ss += v.x*v.x + v.y*v.y + v.z*v.z + v.w*v.w;
    }
    #pragma unroll
    for (int off = 16; off > 0; off >>= 1) ss += __shfl_xor_sync(0xffffffffu, ss, off);
    __shared__ float sw[8]; __shared__ float stot;
    if ((threadIdx.x & 31) == 0) sw[threadIdx.x >> 5] = ss;
    __syncthreads();
    if (threadIdx.x == 0) {
        float t = 0.f;
        #pragma unroll
        for (int i = 0; i < 8; i++) t += sw[i];
        stot = rsqrtf(t / (float)D + 1e-5f);
    }
    __syncthreads();
    const float rs = stot;
    for (int i = threadIdx.x * 4; i < D; i += 256 * 4) {
        float4 v = *(const float4*)(xr + i);
        float4 wv = *(const float4*)(w + i);
        v.x *= rs*wv.x; v.y *= rs*wv.y; v.z *= rs*wv.z; v.w *= rs*wv.w;
        *(float4*)(o + row * D + i) = v;
    }
}

// ---------------- bf16 split kernels ----------------
__device__ __forceinline__ void split4(float4 v, __nv_bfloat16* h, __nv_bfloat16* l, int i) {
    __nv_bfloat16 h0 = __float2bfloat16(v.x), h1 = __float2bfloat16(v.y);
    __nv_bfloat16 h2 = __float2bfloat16(v.z), h3 = __float2bfloat16(v.w);
    __nv_bfloat162 a, b; a.x = h0; a.y = h1; b.x = h2; b.y = h3;
    ((__nv_bfloat162*)h)[2*i]   = a;
    ((__nv_bfloat162*)h)[2*i+1] = b;
    __nv_bfloat162 c, d;
    c.x = __float2bfloat16(v.x - __bfloat162float(h0));
    c.y = __float2bfloat16(v.y - __bfloat162float(h1));
    d.x = __float2bfloat16(v.z - __bfloat162float(h2));
    d.y = __float2bfloat16(v.w - __bfloat162float(h3));
    ((__nv_bfloat162*)l)[2*i]   = c;
    ((__nv_bfloat162*)l)[2*i+1] = d;
}

__global__ void split_k(const float* __restrict__ x,
                        __nv_bfloat16* __restrict__ h, __nv_bfloat16* __restrict__ l, int n4)
{
    int i = blockIdx.x * blockDim.x + threadIdx.x;
    if (i < n4) split4(((const float4*)x)[i], h, l, i);
}

__global__ void split2d_k(const float* __restrict__ x, int ld, int cols4,
                          __nv_bfloat16* __restrict__ h, __nv_bfloat16* __restrict__ l, int n4)
{
    int i = blockIdx.x * blockDim.x + threadIdx.x;
    if (i < n4) {
        int row = i / cols4, c = i % cols4;
        float4 v = *(const float4*)(x + (size_t)row * ld + c * 4);
        split4(v, h, l, i);
    }
}

__global__ void splitmul_k(const float* __restrict__ g, const float* __restrict__ u,
                           __nv_bfloat16* __restrict__ h, __nv_bfloat16* __restrict__ l, int n4)
{
    int i = blockIdx.x * blockDim.x + threadIdx.x;
    if (i < n4) {
        float4 a = ((const float4*)g)[i];
        float4 b = ((const float4*)u)[i];
        a.x *= b.x; a.y *= b.y; a.z *= b.z; a.w *= b.w;
        split4(a, h, l, i);
    }
}

// ---------------- cp.async plane loader: 128 rows x 128B, SW128 swizzled ----------------
__device__ __forceinline__ void ldp(uint32_t sdst, const __nv_bfloat16* __restrict__ g,
                                    int ld, int row0, int k0, int tid)
{
    #pragma unroll
    for (int i = tid; i < 1024; i += 256) {
        int r = i >> 3, u = i & 7;
        const void* src = g + (size_t)(row0 + r) * ld + k0 + u * 8;
        uint32_t dst = sdst + SWZ(r * 128 + u * 16);
        asm volatile("cp.async.cg.shared.global [%0], [%1], 16;" :: "r"(dst), "l"(src));
    }
}

// ---------------- bf16x3 split-precision GEMM via mma.sync ----------------
// C[M,N] = (Ah+Al)[M,K] * (Bh+Bl)[N,K]^T, fp32 accum.
// BM=BN=128, BK=64. 8 warps (2x4), warp tile 64x32 (4x4 m16n8k16).
// 3-stage cp.async ring, ONE __syncthreads per K-chunk.
// EPI: 0=none, 1=softplus(acc+bias[n]), 2=acc+E[m,n], 3=silu(acc)
template<int EPI>
__global__ __launch_bounds__(256, 1)
void gemm_mma(int K,
              const __nv_bfloat16* __restrict__ AH, const __nv_bfloat16* __restrict__ AL,
              const __nv_bfloat16* __restrict__ BH, const __nv_bfloat16* __restrict__ BL,
              float* __restrict__ C, int ldc,
              const float* __restrict__ E, int lde)
{
    extern __shared__ char sm[];
    const int tid = threadIdx.x, wid = tid >> 5, lane = tid & 31;
    const int m0 = blockIdx.x * 128, n0 = blockIdx.y * 128;
    const int wr = wid >> 2, wc = wid & 3;   // warp grid 2x4
    const uint32_t sb = smem_u32(sm);
    constexpr uint32_t PB = 16384, BUF = 4 * PB;   // plane / stage bytes

    float acc[4][4][4];
    #pragma unroll
    for (int a = 0; a < 4; a++)
        #pragma unroll
        for (int b = 0; b < 4; b++)
            #pragma unroll
            for (int c = 0; c < 4; c++) acc[a][b][c] = 0.f;

    const int NC = K >> 6;

    // prologue: chunks 0 and 1 into stages 0 and 1
    ldp(sb + 0*BUF + 0*PB, AH, K, m0, 0, tid);
    ldp(sb + 0*BUF + 1*PB, AL, K, m0, 0, tid);
    ldp(sb + 0*BUF + 2*PB, BH, K, n0, 0, tid);
    ldp(sb + 0*BUF + 3*PB, BL, K, n0, 0, tid);
    asm volatile("cp.async.commit_group;");
    if (NC > 1) {
        ldp(sb + 1*BUF + 0*PB, AH, K, m0, 64, tid);
        ldp(sb + 1*BUF + 1*PB, AL, K, m0, 64, tid);
        ldp(sb + 1*BUF + 2*PB, BH, K, n0, 64, tid);
        ldp(sb + 1*BUF + 3*PB, BL, K, n0, 64, tid);
        asm volatile("cp.async.commit_group;");
    }

    int stage = 0;
    for (int c = 0; c < NC; c++) {
        if (c + 1 < NC) asm volatile("cp.async.wait_group 1;");
        else            asm volatile("cp.async.wait_group 0;");
        __syncthreads();   // chunk c resident; all warps done reading stage (c-1)%3

        // issue chunk c+2 into stage (c+2)%3  (== stage (c-1)%3, now safe)
        if (c + 2 < NC) {
            int ns = stage + 2; if (ns >= 3) ns -= 3;
            const uint32_t nb = sb + (uint32_t)ns * BUF;
            const int k0 = (c + 2) << 6;
            ldp(nb + 0*PB, AH, K, m0, k0, tid);
            ldp(nb + 1*PB, AL, K, m0, k0, tid);
            ldp(nb + 2*PB, BH, K, n0, k0, tid);
            ldp(nb + 3*PB, BL, K, n0, k0, tid);
            asm volatile("cp.async.commit_group;");
        }

        const uint32_t base = sb + (uint32_t)stage * BUF;
        #pragma unroll
        for (int ks = 0; ks < 4; ks++) {
            uint32_t ah[4][4], al[4][4], bh[4][2], bl[4][2];
            // A fragments
            {
                const int row = wr * 64 + (lane & 15);
                const int ku  = ks * 2 + (lane >> 4);
                #pragma unroll
                for (int mt = 0; mt < 4; mt++) {
                    const uint32_t off = SWZ((row + mt * 16) * 128 + ku * 16);
                    LDSM4(ah[mt], base + 0*PB + off);
                    LDSM4(al[mt], base + 1*PB + off);
                }
            }
            // B fragments: each x4 covers two n8 tiles
            {
                const int rn = wc * 32 + (lane & 7) + ((lane >> 4) & 1) * 8;
                const int ku = ks * 2 + ((lane >> 3) & 1);
                #pragma unroll
                for (int p = 0; p < 2; p++) {
                    const uint32_t off = SWZ((rn + p * 16) * 128 + ku * 16);
                    uint32_t t[4];
                    LDSM4(t, base + 2*PB + off);
                    bh[p*2][0] = t[0]; bh[p*2][1] = t[1];
                    bh[p*2+1][0] = t[2]; bh[p*2+1][1] = t[3];
                    LDSM4(t, base + 3*PB + off);
                    bl[p*2][0] = t[0]; bl[p*2][1] = t[1];
                    bl[p*2+1][0] = t[2]; bl[p*2+1][1] = t[3];
                }
            }
            #pragma unroll
            for (int mt = 0; mt < 4; mt++)
                #pragma unroll
                for (int nt = 0; nt < 4; nt++) {
                    MMA16816(acc[mt][nt], ah[mt], bh[nt]);
                    MMA16816(acc[mt][nt], ah[mt], bl[nt]);
                    MMA16816(acc[mt][nt], al[mt], bh[nt]);
                }
        }
        if (++stage == 3) stage = 0;
    }

    // Epilogue: lane l holds (row = l/4 [+8], cols = (l%4)*2, +1)
    #pragma unroll
    for (int mt = 0; mt < 4; mt++) {
        #pragma unroll
        for (int nt = 0; nt < 4; nt++) {
            const int gm = m0 + wr * 64 + mt * 16 + (lane >> 2);
            const int gn = n0 + wc * 32 + nt * 8 + (lane & 3) * 2;
            #pragma unroll
            for (int half = 0; half < 2; half++) {
                const int row = gm + half * 8;
                float2 v = make_float2(acc[mt][nt][half*2], acc[mt][nt][half*2+1]);
                if (EPI == 1) {
                    const float2 b = *(const float2*)(E + gn);
                    v.x = softplusf(v.x + b.x); v.y = softplusf(v.y + b.y);
                } else if (EPI == 2) {
                    const float2 e = *(const float2*)(E + (size_t)row * lde + gn);
                    v.x += e.x; v.y += e.y;
                } else if (EPI == 3) {
                    v.x = siluf(v.x); v.y = siluf(v.y);
                }
                *(float2*)(C + (size_t)row * ldc + gn) = v;
            }
        }
    }
}

// ---------------- Selective scan (verified) ----------------
__global__ void scan_k(const float* __restrict__ zx, const float* __restrict__ dt,
                       const float* __restrict__ A_log, const float* __restrict__ D_skip,
                       float* __restrict__ yg)
{
    const int tid = blockIdx.x * blockDim.x + threadIdx.x;
    const int ch = tid >> 2;
    const int s  = tid & 3;

    const int src  = ((ch >> 6) << 4) + (ch & 15);
    const int boff = 5120 + ((ch >> 6) << 4) + (s << 2);
    const int coff = 6144 + (ch & ~15) + (s << 2);

    const float a0 = -expf(A_log[ch * DSTATE + s * 4 + 0]);
    const float a1 = -expf(A_log[ch * DSTATE + s * 4 + 1]);
    const float a2 = -expf(A_log[ch * DSTATE + s * 4 + 2]);
    const float a3 = -expf(A_log[ch * DSTATE + s * 4 + 3]);
    const float dsk = D_skip[ch];

    float h0 = 0.f, h1 = 0.f, h2 = 0.f, h3 = 0.f;
    const float* row = zx;
    for (int l = 0; l < Lq; l++, row += NPROJ) {
        const float dtv = dt[l * DINNER + ch];
        const float xv  = row[4096 + src];
        const float4 B  = *(const float4*)(row + boff);
        const float4 Cv = *(const float4*)(row + coff);
        const float dtx = dtv * xv;

        h0 = __expf(dtv * a0) * h0 + dtx * B.x;
        h1 = __expf(dtv * a1) * h1 + dtx * B.y;
        h2 = __expf(dtv * a2) * h2 + dtx * B.z;
        h3 = __expf(dtv * a3) * h3 + dtx * B.w;

        float yp = Cv.x * h0 + Cv.y * h1 + Cv.z * h2 + Cv.w * h3;
        yp += __shfl_xor_sync(0xffffffffu, yp, 1);
        yp += __shfl_xor_sync(0xffffffffu, yp, 2);

        if (s == 0) {
            const float z = row[ch];
            float v = yp + dsk * xv;
            v *= z / (1.f + __expf(-z));
            yg[l * DINNER + ch] = v;
        }
    }
}

// ---------------- Launch ----------------
extern "C" void kernel_launch(void* const* d_in, const int* in_sizes, int n_in,
                              void* d_out, int out_size)
{
    const float* hidden     = (const float*)d_in[0];
    const float* rms1_w     = (const float*)d_in[1];
    const float* in_proj_w  = (const float*)d_in[2];
    const float* dt_proj_w  = (const float*)d_in[3];
    const float* dt_proj_b  = (const float*)d_in[4];
    const float* A_log      = (const float*)d_in[5];
    const float* D_skip     = (const float*)d_in[6];
    const float* out_proj_w = (const float*)d_in[7];
    const float* rms2_w     = (const float*)d_in[8];
    const float* gate_w     = (const float*)d_in[9];
    const float* up_w       = (const float*)d_in[10];
    const float* down_w     = (const float*)d_in[11];
    float* out = (float*)d_out;

    float *xn, *zx, *dt, *yg, *h, *hn, *gb, *ub;
    cudaGetSymbolAddress((void**)&xn, g_xn);
    cudaGetSymbolAddress((void**)&zx, g_zx);
    cudaGetSymbolAddress((void**)&dt, g_dt);
    cudaGetSymbolAddress((void**)&yg, g_yg);
    cudaGetSymbolAddress((void**)&h,  g_h);
    cudaGetSymbolAddress((void**)&hn, g_hn);
    cudaGetSymbolAddress((void**)&gb, g_gb);
    cudaGetSymbolAddress((void**)&ub, g_ub);

    __nv_bfloat16 *xnH,*xnL,*dtiH,*dtiL,*ygH,*ygL,*hnH,*hnL,*gpH,*gpL;
    __nv_bfloat16 *wInH,*wInL,*wDtH,*wDtL,*wOutH,*wOutL,*wGH,*wGL,*wUH,*wUL,*wDH,*wDL;
    cudaGetSymbolAddress((void**)&xnH,  g_xnH);  cudaGetSymbolAddress((void**)&xnL,  g_xnL);
    cudaGetSymbolAddress((void**)&dtiH, g_dtiH); cudaGetSymbolAddress((void**)&dtiL, g_dtiL);
    cudaGetSymbolAddress((void**)&ygH,  g_ygH);  cudaGetSymbolAddress((void**)&ygL,  g_ygL);
    cudaGetSymbolAddress((void**)&hnH,  g_hnH);  cudaGetSymbolAddress((void**)&hnL,  g_hnL);
    cudaGetSymbolAddress((void**)&gpH,  g_gpH);  cudaGetSymbolAddress((void**)&gpL,  g_gpL);
    cudaGetSymbolAddress((void**)&wInH, g_wInH); cudaGetSymbolAddress((void**)&wInL, g_wInL);
    cudaGetSymbolAddress((void**)&wDtH, g_wDtH); cudaGetSymbolAddress((void**)&wDtL, g_wDtL);
    cudaGetSymbolAddress((void**)&wOutH,g_wOutH);cudaGetSymbolAddress((void**)&wOutL,g_wOutL);
    cudaGetSymbolAddress((void**)&wGH,  g_wGH);  cudaGetSymbolAddress((void**)&wGL,  g_wGL);
    cudaGetSymbolAddress((void**)&wUH,  g_wUH);  cudaGetSymbolAddress((void**)&wUL,  g_wUL);
    cudaGetSymbolAddress((void**)&wDH,  g_wDH);  cudaGetSymbolAddress((void**)&wDL,  g_wDL);

    const int SMEM = 3 * 4 * 16384;  // 196608 (3-stage ring)
    cudaFuncSetAttribute(gemm_mma<0>, cudaFuncAttributeMaxDynamicSharedMemorySize, SMEM);
    cudaFuncSetAttribute(gemm_mma<1>, cudaFuncAttributeMaxDynamicSharedMemorySize, SMEM);
    cudaFuncSetAttribute(gemm_mma<2>, cudaFuncAttributeMaxDynamicSharedMemorySize, SMEM);
    cudaFuncSetAttribute(gemm_mma<3>, cudaFuncAttributeMaxDynamicSharedMemorySize, SMEM);

    // --- weight splits (memory-bound, ~140us total) ---
    split_k<<<(NPROJ*DMODEL/4 + 255)/256, 256>>>(in_proj_w, wInH, wInL, NPROJ*DMODEL/4);
    split_k<<<(DINNER*DTRANK/4 + 255)/256, 256>>>(dt_proj_w, wDtH, wDtL, DINNER*DTRANK/4);
    split_k<<<(DMODEL*DINNER/4 + 255)/256, 256>>>(out_proj_w, wOutH, wOutL, DMODEL*DINNER/4);
    split_k<<<(INTER*DMODEL/4 + 255)/256, 256>>>(gate_w, wGH, wGL, INTER*DMODEL/4);
    split_k<<<(INTER*DMODEL/4 + 255)/256, 256>>>(up_w, wUH, wUL, INTER*DMODEL/4);
    split_k<<<(DMODEL*INTER/4 + 255)/256, 256>>>(down_w, wDH, wDL, DMODEL*INTER/4);

    // 1. rmsnorm1 + split
    rmsnorm_k<<<Lq, 256>>>(hidden, rms1_w, xn);
    split_k<<<(Lq*DMODEL/4 + 255)/256, 256>>>(xn, xnH, xnL, Lq*DMODEL/4);

    // 2. in_proj: [1024 x 10368], K=2048
    gemm_mma<0><<<dim3(Lq/128, NPROJ/128), 256, SMEM>>>(
        DMODEL, xnH, xnL, wInH, wInL, zx, NPROJ, nullptr, 0);

    // 3. dt = softplus(dt_in @ dt_proj^T + b), K=128
    split2d_k<<<(Lq*DTRANK/4 + 255)/256, 256>>>(
        zx + 2*DINNER + 2*DXB, NPROJ, DTRANK/4, dtiH, dtiL, Lq*DTRANK/4);
    gemm_mma<1><<<dim3(Lq/128, DINNER/128), 256, SMEM>>>(
        DTRANK, dtiH, dtiL, wDtH, wDtL, dt, DINNER, dt_proj_b, 0);

    // 4. selective scan
    scan_k<<<64, 256>>>(zx, dt, A_log, D_skip, yg);

    // 5. out_proj + residual, K=4096
    split_k<<<(Lq*DINNER/4 + 255)/256, 256>>>(yg, ygH, ygL, Lq*DINNER/4);
    gemm_mma<2><<<dim3(Lq/128, DMODEL/128), 256, SMEM>>>(
        DINNER, ygH, ygL, wOutH, wOutL, h, DMODEL, hidden, DMODEL);

    // 6. rmsnorm2 + split
    rmsnorm_k<<<Lq, 256>>>(h, rms2_w, hn);
    split_k<<<(Lq*DMODEL/4 + 255)/256, 256>>>(hn, hnH, hnL, Lq*DMODEL/4);

    // 7/8. gate = silu(hn @ gate^T), up = hn @ up^T, K=2048
    gemm_mma<3><<<dim3(Lq/128, INTER/128), 256, SMEM>>>(
        DMODEL, hnH, hnL, wGH, wGL, gb, INTER, nullptr, 0);
    gemm_mma<0><<<dim3(Lq/128, INTER/128), 256, SMEM>>>(
        DMODEL, hnH, hnL, wUH, wUL, ub, INTER, nullptr, 0);

    // 9. (gate*up) -> bf16 split
    splitmul_k<<<(Lq*INTER/4 + 255)/256, 256>>>(gb, ub, gpH, gpL, Lq*INTER/4);

    // 10. down proj + residual -> out, K=8192
    gemm_mma<2><<<dim3(Lq/128, DMODEL/128), 256, SMEM>>>(
        INTER, gpH, gpL, wDH, wDL, out, DMODEL, h, DMODEL);
}